// round 1
// baseline (speedup 1.0000x reference)
#include <cuda_runtime.h>

// Problem constants
#define BB 8
#define SS 2048
#define DD 512
#define CC 1024   // 2*D

// Scratch (device globals are the sanctioned alloc-free workaround)
__device__ float g_Qcat[(size_t)BB * SS * CC];  // 64 MB  [b, s, 2D]  (Q1 | Q2)
__device__ float g_Kf  [(size_t)BB * SS * DD];  // 32 MB  [b, s, D]
__device__ float g_Vt  [(size_t)BB * DD * SS];  // 32 MB  [b, d, s]  (transposed V)
__device__ float g_P   [(size_t)BB * SS * SS];  // 128 MB [b, q, k]

// ---------------------------------------------------------------------------
// Generic TN SGEMM: C[z] = alpha * A[z] (MxK, row ld=lda) @ B[z]^T (NxK, ld=ldb)
//                   + bias[n] + add1 + add2 (+ C if accumulate)
// Block tile 128x128, k-tile 16, 256 threads, 8x8 per thread, double-buffered.
// M, N implied by grid (must be multiples of 128); K multiple of 16.
// ---------------------------------------------------------------------------
__global__ __launch_bounds__(256) void sgemm_tn(
    const float* __restrict__ A, const float* __restrict__ Bm,
    float* __restrict__ C,
    const float* __restrict__ bias,
    const float* __restrict__ add1, const float* __restrict__ add2,
    int K, int lda, int ldb,
    long long a_bs, long long b_bs, long long c_bs,
    int c_ldm, int c_ldn,
    float alpha, int accumulate)
{
    const int bz = blockIdx.z;
    const float* Ab = A  + (long long)bz * a_bs;
    const float* Bb = Bm + (long long)bz * b_bs;
    const long long cb = (long long)bz * c_bs;

    const int bm = blockIdx.y * 128;
    const int bn = blockIdx.x * 128;

    __shared__ float As[2][16][132];
    __shared__ float Bs[2][16][132];

    const int tid  = threadIdx.x;
    const int rowt = tid >> 4;     // 0..15 -> m sub-block
    const int colt = tid & 15;     // 0..15 -> n sub-block

    // Global->smem load mapping: each thread brings 2 float4 from A, 2 from B.
    const int lm = tid >> 1;            // row within the 128-row tile
    const int lk = (tid & 1) * 8;       // k offset 0 or 8

    const float* aptr = Ab + (long long)(bm + lm) * lda + lk;
    const float* bptr = Bb + (long long)(bn + lm) * ldb + lk;

    float4 pa0, pa1, pb0, pb1;

    float acc[8][8];
#pragma unroll
    for (int i = 0; i < 8; ++i)
#pragma unroll
        for (int j = 0; j < 8; ++j) acc[i][j] = 0.f;

#define LOAD_TILE(kt)                                                    \
    do {                                                                 \
        const float* ap_ = aptr + (kt) * 16;                             \
        const float* bp_ = bptr + (kt) * 16;                             \
        pa0 = *(const float4*)(ap_);                                     \
        pa1 = *(const float4*)(ap_ + 4);                                 \
        pb0 = *(const float4*)(bp_);                                     \
        pb1 = *(const float4*)(bp_ + 4);                                 \
    } while (0)

#define STORE_TILE(buf)                                                  \
    do {                                                                 \
        As[buf][lk + 0][lm] = pa0.x; As[buf][lk + 1][lm] = pa0.y;        \
        As[buf][lk + 2][lm] = pa0.z; As[buf][lk + 3][lm] = pa0.w;        \
        As[buf][lk + 4][lm] = pa1.x; As[buf][lk + 5][lm] = pa1.y;        \
        As[buf][lk + 6][lm] = pa1.z; As[buf][lk + 7][lm] = pa1.w;        \
        Bs[buf][lk + 0][lm] = pb0.x; Bs[buf][lk + 1][lm] = pb0.y;        \
        Bs[buf][lk + 2][lm] = pb0.z; Bs[buf][lk + 3][lm] = pb0.w;        \
        Bs[buf][lk + 4][lm] = pb1.x; Bs[buf][lk + 5][lm] = pb1.y;        \
        Bs[buf][lk + 6][lm] = pb1.z; Bs[buf][lk + 7][lm] = pb1.w;        \
    } while (0)

    const int nk = K >> 4;

    LOAD_TILE(0);
    STORE_TILE(0);
    __syncthreads();

    for (int kt = 0; kt < nk; ++kt) {
        const int cur = kt & 1;
        if (kt + 1 < nk) LOAD_TILE(kt + 1);   // prefetch overlaps compute

#pragma unroll
        for (int k = 0; k < 16; ++k) {
            float4 a0 = *(const float4*)&As[cur][k][rowt * 8];
            float4 a1 = *(const float4*)&As[cur][k][rowt * 8 + 4];
            float4 b0 = *(const float4*)&Bs[cur][k][colt * 8];
            float4 b1 = *(const float4*)&Bs[cur][k][colt * 8 + 4];
            float av[8] = {a0.x, a0.y, a0.z, a0.w, a1.x, a1.y, a1.z, a1.w};
            float bv[8] = {b0.x, b0.y, b0.z, b0.w, b1.x, b1.y, b1.z, b1.w};
#pragma unroll
            for (int i = 0; i < 8; ++i)
#pragma unroll
                for (int j = 0; j < 8; ++j)
                    acc[i][j] = fmaf(av[i], bv[j], acc[i][j]);
        }

        if (kt + 1 < nk) {
            STORE_TILE(cur ^ 1);   // writes the OTHER buffer; safe pre-barrier
            __syncthreads();
        }
    }

    // Epilogue
#pragma unroll
    for (int i = 0; i < 8; ++i) {
        const long long m = bm + rowt * 8 + i;
#pragma unroll
        for (int j = 0; j < 8; ++j) {
            const long long n = bn + colt * 8 + j;
            const long long off = cb + m * (long long)c_ldm + n * (long long)c_ldn;
            float v = alpha * acc[i][j];
            if (bias) v += __ldg(bias + n);
            if (add1) v += add1[off];
            if (add2) v += add2[off];
            if (accumulate) v += C[off];
            C[off] = v;
        }
    }
#undef LOAD_TILE
#undef STORE_TILE
}

// ---------------------------------------------------------------------------
// Row softmax over rows of length 2048 (in place). One block per row.
// ---------------------------------------------------------------------------
__global__ __launch_bounds__(256) void softmax_rows(float* __restrict__ P)
{
    float* p = P + (long long)blockIdx.x * 2048;
    const int t = threadIdx.x;
    __shared__ float red[8];

    float v[8];
    float mx = -3.0e38f;
#pragma unroll
    for (int i = 0; i < 8; ++i) {
        v[i] = p[i * 256 + t];
        mx = fmaxf(mx, v[i]);
    }
#pragma unroll
    for (int o = 16; o > 0; o >>= 1) mx = fmaxf(mx, __shfl_xor_sync(0xffffffffu, mx, o));
    if ((t & 31) == 0) red[t >> 5] = mx;
    __syncthreads();
    mx = red[0];
#pragma unroll
    for (int w = 1; w < 8; ++w) mx = fmaxf(mx, red[w]);
    __syncthreads();   // red reused below

    float s = 0.f;
#pragma unroll
    for (int i = 0; i < 8; ++i) {
        v[i] = __expf(v[i] - mx);
        s += v[i];
    }
#pragma unroll
    for (int o = 16; o > 0; o >>= 1) s += __shfl_xor_sync(0xffffffffu, s, o);
    if ((t & 31) == 0) red[t >> 5] = s;
    __syncthreads();
    s = red[0];
#pragma unroll
    for (int w = 1; w < 8; ++w) s += red[w];

    const float inv = 1.0f / s;
#pragma unroll
    for (int i = 0; i < 8; ++i) p[i * 256 + t] = v[i] * inv;
}

// ---------------------------------------------------------------------------
// Launch sequence
// ---------------------------------------------------------------------------
extern "C" void kernel_launch(void* const* d_in, const int* in_sizes, int n_in,
                              void* d_out, int out_size)
{
    (void)in_sizes; (void)n_in; (void)out_size;

    const float* X    = (const float*)d_in[0];
    const float* Y    = (const float*)d_in[1];
    const float* W_xq = (const float*)d_in[2];
    const float* b_xq = (const float*)d_in[3];
    const float* W_yq = (const float*)d_in[4];
    const float* b_yq = (const float*)d_in[5];
    const float* W_fk = (const float*)d_in[6];
    const float* b_fk = (const float*)d_in[7];
    const float* W_fv = (const float*)d_in[8];
    const float* b_fv = (const float*)d_in[9];
    float* out = (float*)d_out;

    float *Qcat, *Kf, *Vt, *P;
    cudaGetSymbolAddress((void**)&Qcat, g_Qcat);
    cudaGetSymbolAddress((void**)&Kf,   g_Kf);
    cudaGetSymbolAddress((void**)&Vt,   g_Vt);
    cudaGetSymbolAddress((void**)&P,    g_P);

    const float scale = 0.04419417382415922f;  // 1/sqrt(512)
    const dim3 t(256);
    const long long XBS = (long long)SS * DD;   // per-batch stride of X/Y/out/Kf
    const long long QBS = (long long)SS * CC;   // per-batch stride of Qcat
    const long long PBS = (long long)SS * SS;   // per-batch stride of P
    const long long VBS = (long long)DD * SS;   // per-batch stride of Vt

    // 1) Qcat[:, :512] = X @ W_xq^T + b_xq
    sgemm_tn<<<dim3(4, 16, 8), t>>>(X, W_xq, Qcat, b_xq, nullptr, nullptr,
        DD, DD, DD, XBS, 0, QBS, CC, 1, 1.f, 0);
    // 2) Qcat[:, 512:] = Y @ W_yq^T + b_yq
    sgemm_tn<<<dim3(4, 16, 8), t>>>(Y, W_yq, Qcat + DD, b_yq, nullptr, nullptr,
        DD, DD, DD, XBS, 0, QBS, CC, 1, 1.f, 0);
    // 3) Kf = Qcat @ W_fk^T + b_fk
    sgemm_tn<<<dim3(4, 16, 8), t>>>(Qcat, W_fk, Kf, b_fk, nullptr, nullptr,
        CC, CC, CC, QBS, 0, XBS, DD, 1, 1.f, 0);
    // 4) Vt[b][d][s] = (Qcat @ W_fv^T + b_fv) transposed per batch
    sgemm_tn<<<dim3(4, 16, 8), t>>>(Qcat, W_fv, Vt, b_fv, nullptr, nullptr,
        CC, CC, CC, QBS, 0, VBS, 1, SS, 1.f, 0);

    // --- attend(Q1) ---
    // 5) P = scale * Q1 @ Kf^T
    sgemm_tn<<<dim3(16, 16, 8), t>>>(Qcat, Kf, P, nullptr, nullptr, nullptr,
        DD, CC, DD, QBS, XBS, PBS, SS, 1, scale, 0);
    // 6) softmax
    softmax_rows<<<BB * SS, 256>>>(P);
    // 7) out = P @ Vt^T + X + Y
    sgemm_tn<<<dim3(4, 16, 8), t>>>(P, Vt, out, nullptr, X, Y,
        SS, SS, SS, PBS, VBS, XBS, DD, 1, 1.f, 0);

    // --- attend(Q2) ---
    // 8) P = scale * Q2 @ Kf^T
    sgemm_tn<<<dim3(16, 16, 8), t>>>(Qcat + DD, Kf, P, nullptr, nullptr, nullptr,
        DD, CC, DD, QBS, XBS, PBS, SS, 1, scale, 0);
    // 9) softmax
    softmax_rows<<<BB * SS, 256>>>(P);
    // 10) out += P @ Vt^T
    sgemm_tn<<<dim3(4, 16, 8), t>>>(P, Vt, out, nullptr, nullptr, nullptr,
        SS, SS, SS, PBS, VBS, XBS, DD, 1, 1.f, 1);
}

// round 3
// speedup vs baseline: 2.3680x; 2.3680x over previous
#include <cuda_runtime.h>
#include <cuda_bf16.h>
#include <cstdint>

#define BB 8
#define SS 2048
#define DD 512
#define CC 1024

// ---------------------------------------------------------------------------
// Scratch (device globals)
// ---------------------------------------------------------------------------
__device__ unsigned short g_Xhi[(size_t)BB*SS*DD], g_Xlo[(size_t)BB*SS*DD];
__device__ unsigned short g_Yhi[(size_t)BB*SS*DD], g_Ylo[(size_t)BB*SS*DD];
__device__ unsigned short g_Wxqh[DD*DD], g_Wxql[DD*DD];
__device__ unsigned short g_Wyqh[DD*DD], g_Wyql[DD*DD];
__device__ unsigned short g_Wfkh[DD*CC], g_Wfkl[DD*CC];
__device__ unsigned short g_Wfvh[DD*CC], g_Wfvl[DD*CC];
__device__ unsigned short g_Qhi[(size_t)BB*SS*CC], g_Qlo[(size_t)BB*SS*CC];
__device__ unsigned short g_Khi[(size_t)BB*SS*DD], g_Klo[(size_t)BB*SS*DD];
__device__ unsigned short g_Vth[(size_t)BB*DD*SS], g_Vtl[(size_t)BB*DD*SS];
__device__ float          g_P  [(size_t)BB*SS*SS];
__device__ unsigned short g_Phi[(size_t)BB*SS*SS], g_Plo[(size_t)BB*SS*SS];

// ---------------------------------------------------------------------------
// Helpers
// ---------------------------------------------------------------------------
__device__ __forceinline__ uint32_t smem_u32(const void* p) {
    uint32_t a;
    asm("{ .reg .u64 t; cvta.to.shared.u64 t, %1; cvt.u32.u64 %0, t; }"
        : "=r"(a) : "l"(p));
    return a;
}
__device__ __forceinline__ void cp16(uint32_t s, const void* g) {
    asm volatile("cp.async.cg.shared.global [%0], [%1], 16;" :: "r"(s), "l"(g));
}
#define CP_COMMIT() asm volatile("cp.async.commit_group;" ::: "memory")
#define CP_WAIT1()  asm volatile("cp.async.wait_group 1;" ::: "memory")
#define CP_WAIT0()  asm volatile("cp.async.wait_group 0;" ::: "memory")

__device__ __forceinline__ void ldm_x4(uint32_t* r, uint32_t a) {
    asm volatile("ldmatrix.sync.aligned.m8n8.x4.shared.b16 {%0,%1,%2,%3}, [%4];"
        : "=r"(r[0]), "=r"(r[1]), "=r"(r[2]), "=r"(r[3]) : "r"(a));
}
__device__ __forceinline__ void ldm_x2(uint32_t* r, uint32_t a) {
    asm volatile("ldmatrix.sync.aligned.m8n8.x2.shared.b16 {%0,%1}, [%2];"
        : "=r"(r[0]), "=r"(r[1]) : "r"(a));
}
__device__ __forceinline__ void mma_bf16(float* d, const uint32_t* a, const uint32_t* b) {
    asm volatile(
        "mma.sync.aligned.m16n8k16.row.col.f32.bf16.bf16.f32 "
        "{%0,%1,%2,%3}, {%4,%5,%6,%7}, {%8,%9}, {%0,%1,%2,%3};"
        : "+f"(d[0]), "+f"(d[1]), "+f"(d[2]), "+f"(d[3])
        : "r"(a[0]), "r"(a[1]), "r"(a[2]), "r"(a[3]), "r"(b[0]), "r"(b[1]));
}
__device__ __forceinline__ unsigned short hi_bits(float v) {
    return __bfloat16_as_ushort(__float2bfloat16(v));
}
__device__ __forceinline__ unsigned short lo_bits(float v) {
    __nv_bfloat16 h = __float2bfloat16(v);
    return __bfloat16_as_ushort(__float2bfloat16(v - __bfloat162float(h)));
}

// ---------------------------------------------------------------------------
// SMEM layout: 2 buffers x 4 tiles (Ahi,Alo,Bhi,Blo), tile = 128 rows x 32 bf16
// padded to 40 elems/row (conflict-free ldmatrix).
// ---------------------------------------------------------------------------
#define ROWP        40
#define TILE_E      (128 * ROWP)        // 5120 elems
#define TILE_BYTES  (TILE_E * 2)        // 10240 B
#define BUF_BYTES   (4 * TILE_BYTES)    // 40960 B
#define SMEM_TOTAL  (2 * BUF_BYTES)     // 81920 B

// ---------------------------------------------------------------------------
// bf16-split TN GEMM via mma.sync: C = A(MxK) @ B(NxK)^T   (128x128 tile)
// acc = Ahi*Bhi + Ahi*Blo + Alo*Bhi  (~fp32 accuracy)
// mode 0: Cf = alpha*acc
// mode 1: (Chi,Clo) = split(acc + bias[n])
// mode 2: (Chi,Clo) = split(acc + bias[n]) transposed: C[n*cb_ld + m]
// mode 3: Cf = acc + add1? + add2? (+Cf if accumulate)
// ---------------------------------------------------------------------------
__global__ __launch_bounds__(256, 1) void hmma_tn(
    const unsigned short* __restrict__ Ahi, const unsigned short* __restrict__ Alo,
    const unsigned short* __restrict__ Bhi, const unsigned short* __restrict__ Blo,
    int K, int lda, int ldb, long long a_bs, long long b_bs,
    int mode, float alpha, const float* __restrict__ bias,
    float* __restrict__ Cf, long long cf_bs, int cf_ld,
    const float* __restrict__ add1, const float* __restrict__ add2, int accumulate,
    unsigned short* __restrict__ Chi, unsigned short* __restrict__ Clo,
    long long cb_bs, int cb_ld)
{
    extern __shared__ char smem[];
    const uint32_t sbase = smem_u32(smem);

    const int tid  = threadIdx.x;
    const int wid  = tid >> 5;
    const int lane = tid & 31;
    const int warpM = wid >> 2;      // 0..1
    const int warpN = wid & 3;       // 0..3
    const int bz = blockIdx.z;
    const int bm = blockIdx.y * 128, bn = blockIdx.x * 128;

    const unsigned short* gAh = Ahi + (long long)bz * a_bs + (long long)bm * lda;
    const unsigned short* gAl = Alo + (long long)bz * a_bs + (long long)bm * lda;
    const unsigned short* gBh = Bhi + (long long)bz * b_bs + (long long)bn * ldb;
    const unsigned short* gBl = Blo + (long long)bz * b_bs + (long long)bn * ldb;

    float acc[4][4][4];
#pragma unroll
    for (int i = 0; i < 4; ++i)
#pragma unroll
        for (int j = 0; j < 4; ++j)
#pragma unroll
            for (int k = 0; k < 4; ++k) acc[i][j][k] = 0.f;

    const int nch = K >> 5;   // 32-wide k chunks

    // Async load of chunk c into buffer (c&1)
#define LOAD_CHUNK(c)                                                        \
    do {                                                                     \
        const int koff_ = (c) * 32;                                          \
        const uint32_t sb_ = sbase + ((c) & 1) * BUF_BYTES;                  \
        _Pragma("unroll")                                                    \
        for (int h_ = 0; h_ < 2; ++h_) {                                     \
            const int s_ = tid + h_ * 256;                                   \
            const int row_ = s_ >> 2, kseg_ = s_ & 3;                        \
            const uint32_t so_ = (uint32_t)(row_ * ROWP + kseg_ * 8) * 2;    \
            const long long ga_ = (long long)row_ * lda + koff_ + kseg_ * 8; \
            const long long gb_ = (long long)row_ * ldb + koff_ + kseg_ * 8; \
            cp16(sb_ + 0 * TILE_BYTES + so_, gAh + ga_);                     \
            cp16(sb_ + 1 * TILE_BYTES + so_, gAl + ga_);                     \
            cp16(sb_ + 2 * TILE_BYTES + so_, gBh + gb_);                     \
            cp16(sb_ + 3 * TILE_BYTES + so_, gBl + gb_);                     \
        }                                                                    \
        CP_COMMIT();                                                         \
    } while (0)

    LOAD_CHUNK(0);

    for (int c = 0; c < nch; ++c) {
        if (c + 1 < nch) { LOAD_CHUNK(c + 1); CP_WAIT1(); }
        else             { CP_WAIT0(); }
        __syncthreads();

        const uint32_t sb = sbase + (c & 1) * BUF_BYTES;
        const uint32_t aAh = sb + 0 * TILE_BYTES;
        const uint32_t aAl = sb + 1 * TILE_BYTES;
        const uint32_t aBh = sb + 2 * TILE_BYTES;
        const uint32_t aBl = sb + 3 * TILE_BYTES;

#pragma unroll
        for (int ks = 0; ks < 2; ++ks) {
            uint32_t ahi[4][4], alo[4][4], bhi[4][2], blo[4][2];
#pragma unroll
            for (int mi = 0; mi < 4; ++mi) {
                const int row = warpM * 64 + mi * 16 + (lane & 15);
                const int col = ks * 16 + (lane >> 4) * 8;
                const uint32_t off = (uint32_t)(row * ROWP + col) * 2;
                ldm_x4(ahi[mi], aAh + off);
                ldm_x4(alo[mi], aAl + off);
            }
#pragma unroll
            for (int ni = 0; ni < 4; ++ni) {
                const int row = warpN * 32 + ni * 8 + (lane & 7);
                const int col = ks * 16 + ((lane >> 3) & 1) * 8;
                const uint32_t off = (uint32_t)(row * ROWP + col) * 2;
                ldm_x2(bhi[ni], aBh + off);
                ldm_x2(blo[ni], aBl + off);
            }
#pragma unroll
            for (int mi = 0; mi < 4; ++mi)
#pragma unroll
                for (int ni = 0; ni < 4; ++ni) {
                    mma_bf16(acc[mi][ni], ahi[mi], bhi[ni]);
                    mma_bf16(acc[mi][ni], ahi[mi], blo[ni]);
                    mma_bf16(acc[mi][ni], alo[mi], bhi[ni]);
                }
        }
        __syncthreads();
    }
#undef LOAD_CHUNK

    // ------------------------- epilogue (register direct) -------------------
    const int g = lane >> 2, tig = lane & 3;
    const long long cf_off = (long long)bz * cf_bs;
    const long long cb_off = (long long)bz * cb_bs;

#pragma unroll
    for (int mi = 0; mi < 4; ++mi) {
#pragma unroll
        for (int ni = 0; ni < 4; ++ni) {
            const float* a = acc[mi][ni];
            const int m0 = bm + warpM * 64 + mi * 16 + g;
            const int n0 = bn + warpN * 32 + ni * 8 + tig * 2;
#pragma unroll
            for (int half = 0; half < 2; ++half) {
                const int m = m0 + half * 8;
                float v0 = alpha * a[half * 2 + 0];
                float v1 = alpha * a[half * 2 + 1];
                if (mode == 0) {
                    float2 st = make_float2(v0, v1);
                    *(float2*)&Cf[cf_off + (long long)m * cf_ld + n0] = st;
                } else if (mode == 1) {
                    v0 += __ldg(bias + n0);
                    v1 += __ldg(bias + n0 + 1);
                    const long long o = cb_off + (long long)m * cb_ld + n0;
                    *(ushort2*)&Chi[o] = make_ushort2(hi_bits(v0), hi_bits(v1));
                    *(ushort2*)&Clo[o] = make_ushort2(lo_bits(v0), lo_bits(v1));
                } else if (mode == 2) {
                    v0 += __ldg(bias + n0);
                    v1 += __ldg(bias + n0 + 1);
                    const long long o0 = cb_off + (long long)n0 * cb_ld + m;
                    const long long o1 = o0 + cb_ld;
                    Chi[o0] = hi_bits(v0); Clo[o0] = lo_bits(v0);
                    Chi[o1] = hi_bits(v1); Clo[o1] = lo_bits(v1);
                } else {  // mode 3
                    const long long o = cf_off + (long long)m * cf_ld + n0;
                    if (add1) { float2 t = *(const float2*)&add1[o]; v0 += t.x; v1 += t.y; }
                    if (add2) { float2 t = *(const float2*)&add2[o]; v0 += t.x; v1 += t.y; }
                    if (accumulate) { float2 t = *(const float2*)&Cf[o]; v0 += t.x; v1 += t.y; }
                    *(float2*)&Cf[o] = make_float2(v0, v1);
                }
            }
        }
    }
}

// ---------------------------------------------------------------------------
// fp32 -> bf16 hi/lo split
// ---------------------------------------------------------------------------
__global__ __launch_bounds__(256) void split_kernel(
    const float* __restrict__ src,
    unsigned short* __restrict__ hi, unsigned short* __restrict__ lo, int n)
{
    const int i = blockIdx.x * 256 + threadIdx.x;
    if (i < n) {
        const float v = src[i];
        const __nv_bfloat16 h = __float2bfloat16(v);
        hi[i] = __bfloat16_as_ushort(h);
        lo[i] = __bfloat16_as_ushort(__float2bfloat16(v - __bfloat162float(h)));
    }
}

// ---------------------------------------------------------------------------
// Row softmax (rows of 2048): fp32 in -> bf16 hi/lo out
// ---------------------------------------------------------------------------
__global__ __launch_bounds__(256) void softmax_split(
    const float* __restrict__ P,
    unsigned short* __restrict__ Phi, unsigned short* __restrict__ Plo)
{
    const long long rb = (long long)blockIdx.x * 2048;
    const float* p = P + rb;
    const int t = threadIdx.x;
    __shared__ float red[8];

    float v[8];
    float mx = -3.0e38f;
#pragma unroll
    for (int i = 0; i < 8; ++i) {
        v[i] = p[i * 256 + t];
        mx = fmaxf(mx, v[i]);
    }
#pragma unroll
    for (int o = 16; o > 0; o >>= 1) mx = fmaxf(mx, __shfl_xor_sync(0xffffffffu, mx, o));
    if ((t & 31) == 0) red[t >> 5] = mx;
    __syncthreads();
    mx = red[0];
#pragma unroll
    for (int w = 1; w < 8; ++w) mx = fmaxf(mx, red[w]);
    __syncthreads();

    float s = 0.f;
#pragma unroll
    for (int i = 0; i < 8; ++i) {
        v[i] = __expf(v[i] - mx);
        s += v[i];
    }
#pragma unroll
    for (int o = 16; o > 0; o >>= 1) s += __shfl_xor_sync(0xffffffffu, s, o);
    if ((t & 31) == 0) red[t >> 5] = s;
    __syncthreads();
    s = red[0];
#pragma unroll
    for (int w = 1; w < 8; ++w) s += red[w];

    const float inv = 1.0f / s;
#pragma unroll
    for (int i = 0; i < 8; ++i) {
        const float x = v[i] * inv;
        Phi[rb + i * 256 + t] = hi_bits(x);
        Plo[rb + i * 256 + t] = lo_bits(x);
    }
}

// ---------------------------------------------------------------------------
// Launch sequence
// ---------------------------------------------------------------------------
extern "C" void kernel_launch(void* const* d_in, const int* in_sizes, int n_in,
                              void* d_out, int out_size)
{
    (void)in_sizes; (void)n_in; (void)out_size;

    const float* X    = (const float*)d_in[0];
    const float* Y    = (const float*)d_in[1];
    const float* W_xq = (const float*)d_in[2];
    const float* b_xq = (const float*)d_in[3];
    const float* W_yq = (const float*)d_in[4];
    const float* b_yq = (const float*)d_in[5];
    const float* W_fk = (const float*)d_in[6];
    const float* b_fk = (const float*)d_in[7];
    const float* W_fv = (const float*)d_in[8];
    const float* b_fv = (const float*)d_in[9];
    float* out = (float*)d_out;

    unsigned short *Xhi, *Xlo, *Yhi, *Ylo, *Wxqh, *Wxql, *Wyqh, *Wyql;
    unsigned short *Wfkh, *Wfkl, *Wfvh, *Wfvl, *Qhi, *Qlo, *Khi, *Klo;
    unsigned short *Vth, *Vtl, *Phi, *Plo;
    float *P;
    cudaGetSymbolAddress((void**)&Xhi, g_Xhi);   cudaGetSymbolAddress((void**)&Xlo, g_Xlo);
    cudaGetSymbolAddress((void**)&Yhi, g_Yhi);   cudaGetSymbolAddress((void**)&Ylo, g_Ylo);
    cudaGetSymbolAddress((void**)&Wxqh, g_Wxqh); cudaGetSymbolAddress((void**)&Wxql, g_Wxql);
    cudaGetSymbolAddress((void**)&Wyqh, g_Wyqh); cudaGetSymbolAddress((void**)&Wyql, g_Wyql);
    cudaGetSymbolAddress((void**)&Wfkh, g_Wfkh); cudaGetSymbolAddress((void**)&Wfkl, g_Wfkl);
    cudaGetSymbolAddress((void**)&Wfvh, g_Wfvh); cudaGetSymbolAddress((void**)&Wfvl, g_Wfvl);
    cudaGetSymbolAddress((void**)&Qhi, g_Qhi);   cudaGetSymbolAddress((void**)&Qlo, g_Qlo);
    cudaGetSymbolAddress((void**)&Khi, g_Khi);   cudaGetSymbolAddress((void**)&Klo, g_Klo);
    cudaGetSymbolAddress((void**)&Vth, g_Vth);   cudaGetSymbolAddress((void**)&Vtl, g_Vtl);
    cudaGetSymbolAddress((void**)&P,   g_P);
    cudaGetSymbolAddress((void**)&Phi, g_Phi);   cudaGetSymbolAddress((void**)&Plo, g_Plo);

    static int smem_set = 0;
    if (!smem_set) {
        cudaFuncSetAttribute(hmma_tn, cudaFuncAttributeMaxDynamicSharedMemorySize, SMEM_TOTAL);
        smem_set = 1;
    }

    const float scale = 0.04419417382415922f;  // 1/sqrt(512)
    const long long XBS = (long long)SS * DD;
    const long long QBS = (long long)SS * CC;
    const long long PBS = (long long)SS * SS;
    const long long VBS = (long long)DD * SS;

    const int nX = BB * SS * DD;
    split_kernel<<<nX / 256, 256>>>(X, Xhi, Xlo, nX);
    split_kernel<<<nX / 256, 256>>>(Y, Yhi, Ylo, nX);
    split_kernel<<<(DD * DD) / 256, 256>>>(W_xq, Wxqh, Wxql, DD * DD);
    split_kernel<<<(DD * DD) / 256, 256>>>(W_yq, Wyqh, Wyql, DD * DD);
    split_kernel<<<(DD * CC) / 256, 256>>>(W_fk, Wfkh, Wfkl, DD * CC);
    split_kernel<<<(DD * CC) / 256, 256>>>(W_fv, Wfvh, Wfvl, DD * CC);

    // 1) Qcat[:, :512] = X @ W_xq^T + b_xq   (bf16 split out)
    hmma_tn<<<dim3(4, 16, 8), 256, SMEM_TOTAL>>>(
        Xhi, Xlo, Wxqh, Wxql, DD, DD, DD, XBS, 0,
        1, 1.f, b_xq, nullptr, 0, 0, nullptr, nullptr, 0,
        Qhi, Qlo, QBS, CC);
    // 2) Qcat[:, 512:] = Y @ W_yq^T + b_yq
    hmma_tn<<<dim3(4, 16, 8), 256, SMEM_TOTAL>>>(
        Yhi, Ylo, Wyqh, Wyql, DD, DD, DD, XBS, 0,
        1, 1.f, b_yq, nullptr, 0, 0, nullptr, nullptr, 0,
        Qhi + DD, Qlo + DD, QBS, CC);
    // 3) Kf = Qcat @ W_fk^T + b_fk
    hmma_tn<<<dim3(4, 16, 8), 256, SMEM_TOTAL>>>(
        Qhi, Qlo, Wfkh, Wfkl, CC, CC, CC, QBS, 0,
        1, 1.f, b_fk, nullptr, 0, 0, nullptr, nullptr, 0,
        Khi, Klo, XBS, DD);
    // 4) Vt[d][s] = (Qcat @ W_fv^T + b_fv)^T
    hmma_tn<<<dim3(4, 16, 8), 256, SMEM_TOTAL>>>(
        Qhi, Qlo, Wfvh, Wfvl, CC, CC, CC, QBS, 0,
        2, 1.f, b_fv, nullptr, 0, 0, nullptr, nullptr, 0,
        Vth, Vtl, VBS, SS);

    // --- attend(Q1) ---
    hmma_tn<<<dim3(16, 16, 8), 256, SMEM_TOTAL>>>(
        Qhi, Qlo, Khi, Klo, DD, CC, DD, QBS, XBS,
        0, scale, nullptr, P, PBS, SS, nullptr, nullptr, 0,
        nullptr, nullptr, 0, 0);
    softmax_split<<<BB * SS, 256>>>(P, Phi, Plo);
    hmma_tn<<<dim3(4, 16, 8), 256, SMEM_TOTAL>>>(
        Phi, Plo, Vth, Vtl, SS, SS, SS, PBS, VBS,
        3, 1.f, nullptr, out, XBS, DD, X, Y, 0,
        nullptr, nullptr, 0, 0);

    // --- attend(Q2) ---
    hmma_tn<<<dim3(16, 16, 8), 256, SMEM_TOTAL>>>(
        Qhi + DD, Qlo + DD, Khi, Klo, DD, CC, DD, QBS, XBS,
        0, scale, nullptr, P, PBS, SS, nullptr, nullptr, 0,
        nullptr, nullptr, 0, 0);
    softmax_split<<<BB * SS, 256>>>(P, Phi, Plo);
    hmma_tn<<<dim3(4, 16, 8), 256, SMEM_TOTAL>>>(
        Phi, Plo, Vth, Vtl, SS, SS, SS, PBS, VBS,
        3, 1.f, nullptr, out, XBS, DD, nullptr, nullptr, 1,
        nullptr, nullptr, 0, 0);
}

// round 4
// speedup vs baseline: 2.4612x; 1.0393x over previous
#include <cuda_runtime.h>
#include <cuda_bf16.h>
#include <cstdint>

#define BB 8
#define SS 2048
#define DD 512
#define CC 1024

// ---------------------------------------------------------------------------
// Scratch (device globals)
// ---------------------------------------------------------------------------
__device__ unsigned short g_Xhi[(size_t)BB*SS*DD], g_Xlo[(size_t)BB*SS*DD];
__device__ unsigned short g_Yhi[(size_t)BB*SS*DD], g_Ylo[(size_t)BB*SS*DD];
__device__ unsigned short g_Wxqh[DD*DD], g_Wxql[DD*DD];
__device__ unsigned short g_Wyqh[DD*DD], g_Wyql[DD*DD];
__device__ unsigned short g_Wfkh[DD*CC], g_Wfkl[DD*CC];
__device__ unsigned short g_Wfvh[DD*CC], g_Wfvl[DD*CC];
__device__ unsigned short g_Qhi[(size_t)BB*SS*CC], g_Qlo[(size_t)BB*SS*CC];
__device__ unsigned short g_Khi[(size_t)BB*SS*DD], g_Klo[(size_t)BB*SS*DD];
__device__ unsigned short g_Vth[(size_t)BB*DD*SS], g_Vtl[(size_t)BB*DD*SS];
__device__ float          g_P  [(size_t)BB*SS*SS];
__device__ unsigned short g_Phi[(size_t)BB*SS*SS], g_Plo[(size_t)BB*SS*SS];

// ---------------------------------------------------------------------------
// Helpers
// ---------------------------------------------------------------------------
__device__ __forceinline__ uint32_t smem_u32(const void* p) {
    uint32_t a;
    asm("{ .reg .u64 t; cvta.to.shared.u64 t, %1; cvt.u32.u64 %0, t; }"
        : "=r"(a) : "l"(p));
    return a;
}
__device__ __forceinline__ void cp16(uint32_t s, const void* g) {
    asm volatile("cp.async.cg.shared.global [%0], [%1], 16;" :: "r"(s), "l"(g));
}
#define CP_COMMIT() asm volatile("cp.async.commit_group;" ::: "memory")
#define CP_WAIT2()  asm volatile("cp.async.wait_group 2;" ::: "memory")

__device__ __forceinline__ void ldm_x4(uint32_t* r, uint32_t a) {
    asm volatile("ldmatrix.sync.aligned.m8n8.x4.shared.b16 {%0,%1,%2,%3}, [%4];"
        : "=r"(r[0]), "=r"(r[1]), "=r"(r[2]), "=r"(r[3]) : "r"(a));
}
__device__ __forceinline__ void ldm_x2(uint32_t* r, uint32_t a) {
    asm volatile("ldmatrix.sync.aligned.m8n8.x2.shared.b16 {%0,%1}, [%2];"
        : "=r"(r[0]), "=r"(r[1]) : "r"(a));
}
__device__ __forceinline__ void mma_bf16(float* d, const uint32_t* a, const uint32_t* b) {
    asm volatile(
        "mma.sync.aligned.m16n8k16.row.col.f32.bf16.bf16.f32 "
        "{%0,%1,%2,%3}, {%4,%5,%6,%7}, {%8,%9}, {%0,%1,%2,%3};"
        : "+f"(d[0]), "+f"(d[1]), "+f"(d[2]), "+f"(d[3])
        : "r"(a[0]), "r"(a[1]), "r"(a[2]), "r"(a[3]), "r"(b[0]), "r"(b[1]));
}
__device__ __forceinline__ unsigned short hi_bits(float v) {
    return __bfloat16_as_ushort(__float2bfloat16(v));
}
__device__ __forceinline__ unsigned short lo_bits(float v) {
    __nv_bfloat16 h = __float2bfloat16(v);
    return __bfloat16_as_ushort(__float2bfloat16(v - __bfloat162float(h)));
}

// ---------------------------------------------------------------------------
// SMEM: STAGES buffers x 4 tiles (Ahi,Alo,Bhi,Blo); tile = 128 rows x 32 bf16
// padded to 40 elems/row (conflict-free ldmatrix).
// ---------------------------------------------------------------------------
#define STAGES      4
#define ROWP        40
#define TILE_E      (128 * ROWP)        // 5120 elems
#define TILE_BYTES  (TILE_E * 2)        // 10240 B
#define BUF_BYTES   (4 * TILE_BYTES)    // 40960 B
#define SMEM_TOTAL  (STAGES * BUF_BYTES)  // 163840 B

// ---------------------------------------------------------------------------
// bf16-split TN GEMM via mma.sync: C = A(MxK) @ B(NxK)^T   (128x128 tile)
// acc = Ahi*Bhi + Ahi*Blo + Alo*Bhi  (~fp32 accuracy)
// mode 0: Cf = alpha*acc
// mode 1: (Chi,Clo) = split(acc + bias[n])
// mode 2: (Chi,Clo) = split(acc + bias[n]) transposed: C[n*cb_ld + m]
// mode 3: Cf = acc + add1? + add2? (+Cf if accumulate)
// ---------------------------------------------------------------------------
__global__ __launch_bounds__(256, 1) void hmma_tn(
    const unsigned short* __restrict__ Ahi, const unsigned short* __restrict__ Alo,
    const unsigned short* __restrict__ Bhi, const unsigned short* __restrict__ Blo,
    int K, int lda, int ldb, long long a_bs, long long b_bs,
    int mode, float alpha, const float* __restrict__ bias,
    float* __restrict__ Cf, long long cf_bs, int cf_ld,
    const float* __restrict__ add1, const float* __restrict__ add2, int accumulate,
    unsigned short* __restrict__ Chi, unsigned short* __restrict__ Clo,
    long long cb_bs, int cb_ld)
{
    extern __shared__ char smem[];
    const uint32_t sbase = smem_u32(smem);

    const int tid  = threadIdx.x;
    const int wid  = tid >> 5;
    const int lane = tid & 31;
    const int warpM = wid >> 2;      // 0..1
    const int warpN = wid & 3;       // 0..3
    const int bz = blockIdx.z;
    const int bm = blockIdx.y * 128, bn = blockIdx.x * 128;

    const unsigned short* gAh = Ahi + (long long)bz * a_bs + (long long)bm * lda;
    const unsigned short* gAl = Alo + (long long)bz * a_bs + (long long)bm * lda;
    const unsigned short* gBh = Bhi + (long long)bz * b_bs + (long long)bn * ldb;
    const unsigned short* gBl = Blo + (long long)bz * b_bs + (long long)bn * ldb;

    float acc[4][4][4];
#pragma unroll
    for (int i = 0; i < 4; ++i)
#pragma unroll
        for (int j = 0; j < 4; ++j)
#pragma unroll
            for (int k = 0; k < 4; ++k) acc[i][j][k] = 0.f;

    const int nch = K >> 5;   // 32-wide k chunks

    // Per-thread load geometry (2 x cp16 per tile per chunk)
    const int row0 = tid >> 2, kseg0 = tid & 3;              // seg 0..255
    const int row1 = (tid + 256) >> 2, kseg1 = (tid + 256) & 3;
    const uint32_t so0 = (uint32_t)(row0 * ROWP + kseg0 * 8) * 2;
    const uint32_t so1 = (uint32_t)(row1 * ROWP + kseg1 * 8) * 2;

#define LOAD_CHUNK(c)                                                         \
    do {                                                                      \
        const int koff_ = (c) * 32;                                           \
        const uint32_t sb_ = sbase + ((c) % STAGES) * BUF_BYTES;              \
        const long long ga0_ = (long long)row0 * lda + koff_ + kseg0 * 8;     \
        const long long gb0_ = (long long)row0 * ldb + koff_ + kseg0 * 8;     \
        const long long ga1_ = (long long)row1 * lda + koff_ + kseg1 * 8;     \
        const long long gb1_ = (long long)row1 * ldb + koff_ + kseg1 * 8;     \
        cp16(sb_ + 0 * TILE_BYTES + so0, gAh + ga0_);                         \
        cp16(sb_ + 1 * TILE_BYTES + so0, gAl + ga0_);                         \
        cp16(sb_ + 2 * TILE_BYTES + so0, gBh + gb0_);                         \
        cp16(sb_ + 3 * TILE_BYTES + so0, gBl + gb0_);                         \
        cp16(sb_ + 0 * TILE_BYTES + so1, gAh + ga1_);                         \
        cp16(sb_ + 1 * TILE_BYTES + so1, gAl + ga1_);                         \
        cp16(sb_ + 2 * TILE_BYTES + so1, gBh + gb1_);                         \
        cp16(sb_ + 3 * TILE_BYTES + so1, gBl + gb1_);                         \
    } while (0)

    // Prologue: stage chunks 0..STAGES-2 (one commit group each)
#pragma unroll
    for (int s = 0; s < STAGES - 1; ++s) {
        LOAD_CHUNK(s);
        CP_COMMIT();
    }

    // Precompute ldmatrix base offsets (within a tile)
    const int a_row = warpM * 64 + (lane & 15);
    const int a_colsel = (lane >> 4) * 8;
    const int b_row = warpN * 32 + (lane & 7);
    const int b_colsel = ((lane >> 3) & 1) * 8;

    for (int c = 0; c < nch; ++c) {
        CP_WAIT2();            // chunk c resident (<=2 younger groups pending)
        __syncthreads();       // all warps see it; prior reads of reused buf done

        const uint32_t sb = sbase + (c % STAGES) * BUF_BYTES;
        const uint32_t aAh = sb + 0 * TILE_BYTES;
        const uint32_t aAl = sb + 1 * TILE_BYTES;
        const uint32_t aBh = sb + 2 * TILE_BYTES;
        const uint32_t aBl = sb + 3 * TILE_BYTES;

#pragma unroll
        for (int ks = 0; ks < 2; ++ks) {
            uint32_t ahi[4][4], alo[4][4], bhi[4][2], blo[4][2];
#pragma unroll
            for (int mi = 0; mi < 4; ++mi) {
                const int row = a_row + mi * 16;
                const int col = ks * 16 + a_colsel;
                const uint32_t off = (uint32_t)(row * ROWP + col) * 2;
                ldm_x4(ahi[mi], aAh + off);
                ldm_x4(alo[mi], aAl + off);
            }
#pragma unroll
            for (int ni = 0; ni < 4; ++ni) {
                const int row = b_row + ni * 8;
                const int col = ks * 16 + b_colsel;
                const uint32_t off = (uint32_t)(row * ROWP + col) * 2;
                ldm_x2(bhi[ni], aBh + off);
                ldm_x2(blo[ni], aBl + off);
            }
#pragma unroll
            for (int mi = 0; mi < 4; ++mi)
#pragma unroll
                for (int ni = 0; ni < 4; ++ni) {
                    mma_bf16(acc[mi][ni], ahi[mi], bhi[ni]);
                    mma_bf16(acc[mi][ni], ahi[mi], blo[ni]);
                    mma_bf16(acc[mi][ni], alo[mi], bhi[ni]);
                }
        }

        // Issue next load (targets buffer last read at chunk c-1; the barrier
        // at the top of this iteration ordered those reads before these writes)
        if (c + STAGES - 1 < nch) LOAD_CHUNK(c + STAGES - 1);
        CP_COMMIT();   // exactly one group per iteration keeps wait accounting
    }
#undef LOAD_CHUNK

    // ------------------------- epilogue (register direct) -------------------
    const int g = lane >> 2, tig = lane & 3;
    const long long cf_off = (long long)bz * cf_bs;
    const long long cb_off = (long long)bz * cb_bs;

#pragma unroll
    for (int mi = 0; mi < 4; ++mi) {
#pragma unroll
        for (int ni = 0; ni < 4; ++ni) {
            const float* a = acc[mi][ni];
            const int m0 = bm + warpM * 64 + mi * 16 + g;
            const int n0 = bn + warpN * 32 + ni * 8 + tig * 2;
#pragma unroll
            for (int half = 0; half < 2; ++half) {
                const int m = m0 + half * 8;
                float v0 = alpha * a[half * 2 + 0];
                float v1 = alpha * a[half * 2 + 1];
                if (mode == 0) {
                    *(float2*)&Cf[cf_off + (long long)m * cf_ld + n0] =
                        make_float2(v0, v1);
                } else if (mode == 1) {
                    v0 += __ldg(bias + n0);
                    v1 += __ldg(bias + n0 + 1);
                    const long long o = cb_off + (long long)m * cb_ld + n0;
                    *(ushort2*)&Chi[o] = make_ushort2(hi_bits(v0), hi_bits(v1));
                    *(ushort2*)&Clo[o] = make_ushort2(lo_bits(v0), lo_bits(v1));
                } else if (mode == 2) {
                    v0 += __ldg(bias + n0);
                    v1 += __ldg(bias + n0 + 1);
                    const long long o0 = cb_off + (long long)n0 * cb_ld + m;
                    const long long o1 = o0 + cb_ld;
                    Chi[o0] = hi_bits(v0); Clo[o0] = lo_bits(v0);
                    Chi[o1] = hi_bits(v1); Clo[o1] = lo_bits(v1);
                } else {  // mode 3
                    const long long o = cf_off + (long long)m * cf_ld + n0;
                    if (add1) { float2 t = *(const float2*)&add1[o]; v0 += t.x; v1 += t.y; }
                    if (add2) { float2 t = *(const float2*)&add2[o]; v0 += t.x; v1 += t.y; }
                    if (accumulate) { float2 t = *(const float2*)&Cf[o]; v0 += t.x; v1 += t.y; }
                    *(float2*)&Cf[o] = make_float2(v0, v1);
                }
            }
        }
    }
}

// ---------------------------------------------------------------------------
// fp32 -> bf16 hi/lo split
// ---------------------------------------------------------------------------
__global__ __launch_bounds__(256) void split_kernel(
    const float* __restrict__ src,
    unsigned short* __restrict__ hi, unsigned short* __restrict__ lo, int n)
{
    const int i = blockIdx.x * 256 + threadIdx.x;
    if (i < n) {
        const float v = src[i];
        const __nv_bfloat16 h = __float2bfloat16(v);
        hi[i] = __bfloat16_as_ushort(h);
        lo[i] = __bfloat16_as_ushort(__float2bfloat16(v - __bfloat162float(h)));
    }
}

// ---------------------------------------------------------------------------
// Row softmax (rows of 2048): fp32 in -> bf16 hi/lo out
// ---------------------------------------------------------------------------
__global__ __launch_bounds__(256) void softmax_split(
    const float* __restrict__ P,
    unsigned short* __restrict__ Phi, unsigned short* __restrict__ Plo)
{
    const long long rb = (long long)blockIdx.x * 2048;
    const float* p = P + rb;
    const int t = threadIdx.x;
    __shared__ float red[8];

    float v[8];
    float mx = -3.0e38f;
#pragma unroll
    for (int i = 0; i < 8; ++i) {
        v[i] = p[i * 256 + t];
        mx = fmaxf(mx, v[i]);
    }
#pragma unroll
    for (int o = 16; o > 0; o >>= 1) mx = fmaxf(mx, __shfl_xor_sync(0xffffffffu, mx, o));
    if ((t & 31) == 0) red[t >> 5] = mx;
    __syncthreads();
    mx = red[0];
#pragma unroll
    for (int w = 1; w < 8; ++w) mx = fmaxf(mx, red[w]);
    __syncthreads();

    float s = 0.f;
#pragma unroll
    for (int i = 0; i < 8; ++i) {
        v[i] = __expf(v[i] - mx);
        s += v[i];
    }
#pragma unroll
    for (int o = 16; o > 0; o >>= 1) s += __shfl_xor_sync(0xffffffffu, s, o);
    if ((t & 31) == 0) red[t >> 5] = s;
    __syncthreads();
    s = red[0];
#pragma unroll
    for (int w = 1; w < 8; ++w) s += red[w];

    const float inv = 1.0f / s;
#pragma unroll
    for (int i = 0; i < 8; ++i) {
        const float x = v[i] * inv;
        Phi[rb + i * 256 + t] = hi_bits(x);
        Plo[rb + i * 256 + t] = lo_bits(x);
    }
}

// ---------------------------------------------------------------------------
// Launch sequence
// ---------------------------------------------------------------------------
extern "C" void kernel_launch(void* const* d_in, const int* in_sizes, int n_in,
                              void* d_out, int out_size)
{
    (void)in_sizes; (void)n_in; (void)out_size;

    const float* X    = (const float*)d_in[0];
    const float* Y    = (const float*)d_in[1];
    const float* W_xq = (const float*)d_in[2];
    const float* b_xq = (const float*)d_in[3];
    const float* W_yq = (const float*)d_in[4];
    const float* b_yq = (const float*)d_in[5];
    const float* W_fk = (const float*)d_in[6];
    const float* b_fk = (const float*)d_in[7];
    const float* W_fv = (const float*)d_in[8];
    const float* b_fv = (const float*)d_in[9];
    float* out = (float*)d_out;

    unsigned short *Xhi, *Xlo, *Yhi, *Ylo, *Wxqh, *Wxql, *Wyqh, *Wyql;
    unsigned short *Wfkh, *Wfkl, *Wfvh, *Wfvl, *Qhi, *Qlo, *Khi, *Klo;
    unsigned short *Vth, *Vtl, *Phi, *Plo;
    float *P;
    cudaGetSymbolAddress((void**)&Xhi, g_Xhi);   cudaGetSymbolAddress((void**)&Xlo, g_Xlo);
    cudaGetSymbolAddress((void**)&Yhi, g_Yhi);   cudaGetSymbolAddress((void**)&Ylo, g_Ylo);
    cudaGetSymbolAddress((void**)&Wxqh, g_Wxqh); cudaGetSymbolAddress((void**)&Wxql, g_Wxql);
    cudaGetSymbolAddress((void**)&Wyqh, g_Wyqh); cudaGetSymbolAddress((void**)&Wyql, g_Wyql);
    cudaGetSymbolAddress((void**)&Wfkh, g_Wfkh); cudaGetSymbolAddress((void**)&Wfkl, g_Wfkl);
    cudaGetSymbolAddress((void**)&Wfvh, g_Wfvh); cudaGetSymbolAddress((void**)&Wfvl, g_Wfvl);
    cudaGetSymbolAddress((void**)&Qhi, g_Qhi);   cudaGetSymbolAddress((void**)&Qlo, g_Qlo);
    cudaGetSymbolAddress((void**)&Khi, g_Khi);   cudaGetSymbolAddress((void**)&Klo, g_Klo);
    cudaGetSymbolAddress((void**)&Vth, g_Vth);   cudaGetSymbolAddress((void**)&Vtl, g_Vtl);
    cudaGetSymbolAddress((void**)&P,   g_P);
    cudaGetSymbolAddress((void**)&Phi, g_Phi);   cudaGetSymbolAddress((void**)&Plo, g_Plo);

    cudaFuncSetAttribute(hmma_tn, cudaFuncAttributeMaxDynamicSharedMemorySize, SMEM_TOTAL);

    const float scale = 0.04419417382415922f;  // 1/sqrt(512)
    const long long XBS = (long long)SS * DD;
    const long long QBS = (long long)SS * CC;
    const long long PBS = (long long)SS * SS;
    const long long VBS = (long long)DD * SS;

    const int nX = BB * SS * DD;
    split_kernel<<<nX / 256, 256>>>(X, Xhi, Xlo, nX);
    split_kernel<<<nX / 256, 256>>>(Y, Yhi, Ylo, nX);
    split_kernel<<<(DD * DD) / 256, 256>>>(W_xq, Wxqh, Wxql, DD * DD);
    split_kernel<<<(DD * DD) / 256, 256>>>(W_yq, Wyqh, Wyql, DD * DD);
    split_kernel<<<(DD * CC) / 256, 256>>>(W_fk, Wfkh, Wfkl, DD * CC);
    split_kernel<<<(DD * CC) / 256, 256>>>(W_fv, Wfvh, Wfvl, DD * CC);

    // 1) Qcat[:, :512] = X @ W_xq^T + b_xq   (bf16 split out)
    hmma_tn<<<dim3(4, 16, 8), 256, SMEM_TOTAL>>>(
        Xhi, Xlo, Wxqh, Wxql, DD, DD, DD, XBS, 0,
        1, 1.f, b_xq, nullptr, 0, 0, nullptr, nullptr, 0,
        Qhi, Qlo, QBS, CC);
    // 2) Qcat[:, 512:] = Y @ W_yq^T + b_yq
    hmma_tn<<<dim3(4, 16, 8), 256, SMEM_TOTAL>>>(
        Yhi, Ylo, Wyqh, Wyql, DD, DD, DD, XBS, 0,
        1, 1.f, b_yq, nullptr, 0, 0, nullptr, nullptr, 0,
        Qhi + DD, Qlo + DD, QBS, CC);
    // 3) Kf = Qcat @ W_fk^T + b_fk
    hmma_tn<<<dim3(4, 16, 8), 256, SMEM_TOTAL>>>(
        Qhi, Qlo, Wfkh, Wfkl, CC, CC, CC, QBS, 0,
        1, 1.f, b_fk, nullptr, 0, 0, nullptr, nullptr, 0,
        Khi, Klo, XBS, DD);
    // 4) Vt[d][s] = (Qcat @ W_fv^T + b_fv)^T
    hmma_tn<<<dim3(4, 16, 8), 256, SMEM_TOTAL>>>(
        Qhi, Qlo, Wfvh, Wfvl, CC, CC, CC, QBS, 0,
        2, 1.f, b_fv, nullptr, 0, 0, nullptr, nullptr, 0,
        Vth, Vtl, VBS, SS);

    // --- attend(Q1) ---
    hmma_tn<<<dim3(16, 16, 8), 256, SMEM_TOTAL>>>(
        Qhi, Qlo, Khi, Klo, DD, CC, DD, QBS, XBS,
        0, scale, nullptr, P, PBS, SS, nullptr, nullptr, 0,
        nullptr, nullptr, 0, 0);
    softmax_split<<<BB * SS, 256>>>(P, Phi, Plo);
    hmma_tn<<<dim3(4, 16, 8), 256, SMEM_TOTAL>>>(
        Phi, Plo, Vth, Vtl, SS, SS, SS, PBS, VBS,
        3, 1.f, nullptr, out, XBS, DD, X, Y, 0,
        nullptr, nullptr, 0, 0);

    // --- attend(Q2) ---
    hmma_tn<<<dim3(16, 16, 8), 256, SMEM_TOTAL>>>(
        Qhi + DD, Qlo + DD, Khi, Klo, DD, CC, DD, QBS, XBS,
        0, scale, nullptr, P, PBS, SS, nullptr, nullptr, 0,
        nullptr, nullptr, 0, 0);
    softmax_split<<<BB * SS, 256>>>(P, Phi, Plo);
    hmma_tn<<<dim3(4, 16, 8), 256, SMEM_TOTAL>>>(
        Phi, Plo, Vth, Vtl, SS, SS, SS, PBS, VBS,
        3, 1.f, nullptr, out, XBS, DD, nullptr, nullptr, 1,
        nullptr, nullptr, 0, 0);
}